// round 2
// baseline (speedup 1.0000x reference)
#include <cuda_runtime.h>
#include <cstddef>

#define Bn 16
#define Nn 2048
#define Cn 128
#define NP 512
#define CIN 131
#define PROW 132
#define NROWS (3*Bn*NP)

typedef unsigned long long ull;

#define FMA2(d,a,b,c) asm("fma.rn.f32x2 %0,%1,%2,%3;" : "=l"(d) : "l"(a), "l"(b), "l"(c))

__device__ __forceinline__ ull pack2(float lo, float hi) {
    ull r; asm("mov.b64 %0,{%1,%2};" : "=l"(r) : "f"(lo), "f"(hi)); return r;
}
__device__ __forceinline__ void unpack2(ull v, float& lo, float& hi) {
    asm("mov.b64 {%0,%1},%2;" : "=f"(lo), "=f"(hi) : "l"(v));
}

__device__ float g_featT[Bn*Nn*Cn];      // features transposed (B,N,C)
__device__ float g_pooled[NROWS*PROW];   // pooled rows (row = s*8192 + b*512 + p)

// ---------------------------------------------------------------------------
// K0: transpose features (B,C,N) -> featT (B,N,C)
// ---------------------------------------------------------------------------
__global__ void k_transpose(const float* __restrict__ f) {
    __shared__ float tile[32][33];
    int b  = blockIdx.z;
    int c0 = blockIdx.x * 32, n0 = blockIdx.y * 32;
    int tx = threadIdx.x, ty = threadIdx.y;
    const float* src = f + (size_t)b * Cn * Nn;
    float* dst = g_featT + (size_t)b * Nn * Cn;
#pragma unroll
    for (int j = 0; j < 32; j += 8)
        tile[ty + j][tx] = src[(size_t)(c0 + ty + j) * Nn + n0 + tx];
    __syncthreads();
#pragma unroll
    for (int j = 0; j < 32; j += 8)
        dst[(size_t)(n0 + ty + j) * Cn + c0 + tx] = tile[tx][ty + j];
}

// ---------------------------------------------------------------------------
// K1: farthest point sampling — one BAR/iter via double-buffered partials.
// Bit-exact distances, ties -> lowest index.
// ---------------------------------------------------------------------------
__global__ __launch_bounds__(1024) void k_fps(const float* __restrict__ xyz,
                                              float* __restrict__ out_xyz) {
    __shared__ float xs[Nn], ys[Nn], zs[Nn];
    __shared__ float rv[2][32];
    __shared__ int   ri[2][32];
    int b = blockIdx.x, tid = threadIdx.x;
    int lane = tid & 31, wid = tid >> 5;
    const float* src = xyz + (size_t)b * Nn * 3;
    for (int t = tid; t < Nn; t += 1024) {
        xs[t] = src[t*3 + 0]; ys[t] = src[t*3 + 1]; zs[t] = src[t*3 + 2];
    }
    __syncthreads();
    int i0 = tid, i1 = tid + 1024;
    float x0 = xs[i0], y0 = ys[i0], z0 = zs[i0];
    float x1 = xs[i1], y1 = ys[i1], z1 = zs[i1];
    float d0 = 1e10f, d1 = 1e10f;
    int last = 0;
    if (tid == 0) {
        out_xyz[(size_t)b*NP*3 + 0] = xs[0];
        out_xyz[(size_t)b*NP*3 + 1] = ys[0];
        out_xyz[(size_t)b*NP*3 + 2] = zs[0];
    }
    for (int it = 1; it < NP; ++it) {
        float px = xs[last], py = ys[last], pz = zs[last];
        float ax = x0 - px, ay = y0 - py, az = z0 - pz;
        float dd = __fadd_rn(__fadd_rn(__fmul_rn(ax,ax), __fmul_rn(ay,ay)), __fmul_rn(az,az));
        d0 = fminf(d0, dd);
        ax = x1 - px; ay = y1 - py; az = z1 - pz;
        dd = __fadd_rn(__fadd_rn(__fmul_rn(ax,ax), __fmul_rn(ay,ay)), __fmul_rn(az,az));
        d1 = fminf(d1, dd);
        float v; int ix;
        if (d1 > d0) { v = d1; ix = i1; } else { v = d0; ix = i0; }
#pragma unroll
        for (int off = 16; off; off >>= 1) {
            float ov = __shfl_xor_sync(0xffffffffu, v, off);
            int   oi = __shfl_xor_sync(0xffffffffu, ix, off);
            if (ov > v || (ov == v && oi < ix)) { v = ov; ix = oi; }
        }
        int bufi = it & 1;
        if (lane == 0) { rv[bufi][wid] = v; ri[bufi][wid] = ix; }
        __syncthreads();
        v = rv[bufi][lane]; ix = ri[bufi][lane];
#pragma unroll
        for (int off = 16; off; off >>= 1) {
            float ov = __shfl_xor_sync(0xffffffffu, v, off);
            int   oi = __shfl_xor_sync(0xffffffffu, ix, off);
            if (ov > v || (ov == v && oi < ix)) { v = ov; ix = oi; }
        }
        last = ix;
        if (tid == 0) {
            out_xyz[(size_t)(b*NP + it)*3 + 0] = xs[ix];
            out_xyz[(size_t)(b*NP + it)*3 + 1] = ys[ix];
            out_xyz[(size_t)(b*NP + it)*3 + 2] = zs[ix];
        }
    }
}

// ---------------------------------------------------------------------------
// K2: ball query (warps 0-2) + MLP via fma.f32x2 (8 samples/group, duplicated
// W2 in smem) + register max-pool, static scale->warp map, NO atomics.
// 192 threads/block, one block per (b, center).
// ---------------------------------------------------------------------------
__global__ __launch_bounds__(192) void k_msg(const float* __restrict__ xyz,
                                             const float* __restrict__ W1,
                                             const float* __restrict__ b1,
                                             const float* __restrict__ W2,
                                             const float* __restrict__ b2,
                                             const float* __restrict__ new_xyz) {
    __shared__ __align__(16) ull   W2d[32*CIN];   // duplicated (w,w) pairs
    __shared__ ull   b2d[CIN];
    __shared__ float W1s[320];
    __shared__ float b1s[32];
    __shared__ __align__(16) float h1buf[6*32*8]; // [warp][m][q]
    __shared__ float rel_sh[6][8][3];
    __shared__ float pw[6*160];
    __shared__ int   idx_sh[96];

    int tid = threadIdx.x, lane = tid & 31, w = tid >> 5;
    int blk = blockIdx.x, b = blk >> 9;
    const float* bp = xyz + (size_t)b * Nn * 3;

    for (int j = tid; j < 32*CIN; j += 192) {
        int m = j / CIN, c = j - m*CIN;
        float v = W2[m*CIN + c];
        W2d[j] = pack2(v, v);
    }
    for (int j = tid; j < CIN; j += 192) { float v = b2[j]; b2d[j] = pack2(v, v); }
    for (int j = tid; j < 320; j += 192) W1s[j] = W1[j];
    if (tid < 32) b1s[tid] = b1[tid];

    float cx = new_xyz[(size_t)blk*3 + 0];
    float cy = new_xyz[(size_t)blk*3 + 1];
    float cz = new_xyz[(size_t)blk*3 + 2];

    // ---- ball query (ascending first-ns, pad with first) ----
    if (w < 3) {
        const float thr = (w == 0) ? (float)(0.1*0.1) : (w == 1) ? (float)(0.2*0.2) : (float)(0.4*0.4);
        const int   ns  = (w == 0) ? 16 : (w == 1) ? 32 : 48;
        const int   off = (w == 0) ? 0  : (w == 1) ? 16 : 48;
        int cnt = 0;
#pragma unroll 1
        for (int ch = 0; ch < 16; ++ch) {
            if (cnt >= ns) break;
            float d2v[4];
#pragma unroll
            for (int u = 0; u < 4; ++u) {
                int i = (ch*4 + u)*32 + lane;
                float qx = bp[i*3 + 0], qy = bp[i*3 + 1], qz = bp[i*3 + 2];
                float ax = cx - qx, ay = cy - qy, az = cz - qz;
                d2v[u] = __fadd_rn(__fadd_rn(__fmul_rn(ax,ax), __fmul_rn(ay,ay)), __fmul_rn(az,az));
            }
#pragma unroll
            for (int u = 0; u < 4; ++u) {
                bool pr = d2v[u] < thr;
                unsigned mk = __ballot_sync(0xffffffffu, pr);
                if (pr) {
                    int pos = cnt + __popc(mk & ((1u << lane) - 1u));
                    if (pos < ns) idx_sh[off + pos] = (ch*4 + u)*32 + lane;
                }
                cnt += __popc(mk);
            }
        }
        __syncwarp();
        if (cnt < ns) {
            int f0 = idx_sh[off];
            for (int q = cnt + lane; q < ns; q += 32) idx_sh[off + q] = f0;
        }
    }
    __syncthreads();

    // ---- static scale->warp map: w0->s0, w1,w2->s1, w3..5->s2, 2x8 samples each
    int s    = (w == 0) ? 0 : (w < 3) ? 1 : 2;
    int sb   = (s == 0) ? 0 : (s == 1) ? 16 : 48;
    int base = (s == 1) ? (w - 1)*16 : (s == 2) ? (w - 3)*16 : 0;

    const float* ftb = g_featT + (size_t)b * Nn * Cn;
    float lmax[5] = {0.f, 0.f, 0.f, 0.f, 0.f};

    for (int g2 = 0; g2 < 2; ++g2) {
        int j0 = base + g2*8;
        int sidx[8];
        float h1v[8];
#pragma unroll
        for (int q = 0; q < 8; ++q) {
            int ii = idx_sh[sb + j0 + q];
            sidx[q] = ii;
            float gx = bp[ii*3 + 0], gy = bp[ii*3 + 1], gz = bp[ii*3 + 2];
            float rx = gx - cx, ry = gy - cy, rz = gz - cz;
            if (lane == q) { rel_sh[w][q][0] = rx; rel_sh[w][q][1] = ry; rel_sh[w][q][2] = rz; }
            float dn = sqrtf(rx*rx + ry*ry + rz*rz);
            float a = b1s[lane];
            a = fmaf(dn, W1s[0*32 + lane], a);
            a = fmaf(cx, W1s[1*32 + lane], a);
            a = fmaf(cy, W1s[2*32 + lane], a);
            a = fmaf(cz, W1s[3*32 + lane], a);
            a = fmaf(gx, W1s[4*32 + lane], a);
            a = fmaf(gy, W1s[5*32 + lane], a);
            a = fmaf(gz, W1s[6*32 + lane], a);
            a = fmaf(rx, W1s[7*32 + lane], a);
            a = fmaf(ry, W1s[8*32 + lane], a);
            a = fmaf(rz, W1s[9*32 + lane], a);
            h1v[q] = fmaxf(a, 0.f);
        }
        __syncwarp();
        {
            float* hb = &h1buf[(w*32 + lane)*8];
            *(float4*)hb       = make_float4(h1v[0], h1v[1], h1v[2], h1v[3]);
            *(float4*)(hb + 4) = make_float4(h1v[4], h1v[5], h1v[6], h1v[7]);
        }
        __syncwarp();

        ull acc[5][4];
        {
            ull b0 = b2d[lane];
            ull bb1 = b2d[32 + lane];
            ull bb2 = b2d[64 + lane];
            ull bb3 = b2d[96 + lane];
            ull bb4 = (lane < 3) ? b2d[128 + lane] : 0ULL;
#pragma unroll
            for (int p = 0; p < 4; ++p) {
                acc[0][p] = b0; acc[1][p] = bb1; acc[2][p] = bb2; acc[3][p] = bb3; acc[4][p] = bb4;
            }
        }
#pragma unroll 8
        for (int m = 0; m < 32; ++m) {
            const ulonglong2* hp = (const ulonglong2*)&h1buf[(w*32 + m)*8];
            ulonglong2 Ha = hp[0];
            ulonglong2 Hb = hp[1];
            const ull* wrow = &W2d[m*CIN];
            ull w0 = wrow[lane];
            ull w1_ = wrow[32 + lane];
            ull w2_ = wrow[64 + lane];
            ull w3_ = wrow[96 + lane];
            FMA2(acc[0][0], w0,  Ha.x, acc[0][0]);
            FMA2(acc[0][1], w0,  Ha.y, acc[0][1]);
            FMA2(acc[0][2], w0,  Hb.x, acc[0][2]);
            FMA2(acc[0][3], w0,  Hb.y, acc[0][3]);
            FMA2(acc[1][0], w1_, Ha.x, acc[1][0]);
            FMA2(acc[1][1], w1_, Ha.y, acc[1][1]);
            FMA2(acc[1][2], w1_, Hb.x, acc[1][2]);
            FMA2(acc[1][3], w1_, Hb.y, acc[1][3]);
            FMA2(acc[2][0], w2_, Ha.x, acc[2][0]);
            FMA2(acc[2][1], w2_, Ha.y, acc[2][1]);
            FMA2(acc[2][2], w2_, Hb.x, acc[2][2]);
            FMA2(acc[2][3], w2_, Hb.y, acc[2][3]);
            FMA2(acc[3][0], w3_, Ha.x, acc[3][0]);
            FMA2(acc[3][1], w3_, Ha.y, acc[3][1]);
            FMA2(acc[3][2], w3_, Hb.x, acc[3][2]);
            FMA2(acc[3][3], w3_, Hb.y, acc[3][3]);
            if (lane < 3) {
                ull w4_ = wrow[128 + lane];
                FMA2(acc[4][0], w4_, Ha.x, acc[4][0]);
                FMA2(acc[4][1], w4_, Ha.y, acc[4][1]);
                FMA2(acc[4][2], w4_, Hb.x, acc[4][2]);
                FMA2(acc[4][3], w4_, Hb.y, acc[4][3]);
            }
        }

        // epilogue: relu(h*x) running max
#pragma unroll
        for (int i = 0; i < 5; ++i) {
            int c = i*32 + lane;
            if (c < CIN) {
#pragma unroll
                for (int p = 0; p < 4; ++p) {
                    float hlo, hhi;
                    unpack2(acc[i][p], hlo, hhi);
                    int q0 = 2*p, q1 = 2*p + 1;
                    float x0, x1;
                    if (i == 0) {
                        if (c >= 3) {
                            x0 = ftb[(size_t)sidx[q0]*Cn + c - 3];
                            x1 = ftb[(size_t)sidx[q1]*Cn + c - 3];
                        } else {
                            x0 = rel_sh[w][q0][c];
                            x1 = rel_sh[w][q1][c];
                        }
                    } else {
                        x0 = ftb[(size_t)sidx[q0]*Cn + c - 3];
                        x1 = ftb[(size_t)sidx[q1]*Cn + c - 3];
                    }
                    lmax[i] = fmaxf(lmax[i], fmaxf(hlo*x0, hhi*x1));
                }
            }
        }
    }
#pragma unroll
    for (int i = 0; i < 5; ++i) pw[w*160 + i*32 + lane] = lmax[i];
    __syncthreads();

    // merge warps of same scale, write g_pooled
    for (int o = tid; o < 3*CIN; o += 192) {
        int sc = o / CIN, c = o - sc*CIN;
        float v;
        if (sc == 0)      v = pw[0*160 + c];
        else if (sc == 1) v = fmaxf(pw[1*160 + c], pw[2*160 + c]);
        else              v = fmaxf(fmaxf(pw[3*160 + c], pw[4*160 + c]), pw[5*160 + c]);
        g_pooled[(size_t)(sc*8192 + blk)*PROW + c] = v;
    }
}

// ---------------------------------------------------------------------------
// K3: out = relu(pooled @ Wcr + bcr) via fma.f32x2 with duplicated W panels.
// M=24576, K=131, N=128. Writes new_features[b][s*128+o][p].
// ---------------------------------------------------------------------------
__global__ __launch_bounds__(256) void k_proj(const float* __restrict__ Wcr,
                                              const float* __restrict__ bcr,
                                              float* __restrict__ outF) {
    __shared__ __align__(16) float Ps[131*36];   // [k][r], stride 36
    __shared__ __align__(16) ull   Wpd[16*128];  // duplicated W panel
    __shared__ float bs[128];
    int tid = threadIdx.x;
    int row0 = blockIdx.x * 32;
    for (int idx = tid; idx < 32*131; idx += 256) {
        int r = idx / 131, k = idx - r*131;
        Ps[k*36 + r] = g_pooled[(size_t)(row0 + r)*PROW + k];
    }
    if (tid < 128) bs[tid] = bcr[tid];

    ull acc[2][4];
#pragma unroll
    for (int p = 0; p < 2; ++p)
#pragma unroll
        for (int o = 0; o < 4; ++o) acc[p][o] = 0ULL;

    int cg = tid & 31, rg = tid >> 5;
    for (int kp = 0; kp < 9; ++kp) {
        int kb = kp*16;
        int klen = (kp == 8) ? 3 : 16;
        __syncthreads();
        for (int j = tid; j < klen*128; j += 256) {
            float v = Wcr[kb*128 + j];
            Wpd[j] = pack2(v, v);
        }
        __syncthreads();
#pragma unroll 4
        for (int kk = 0; kk < 16; ++kk) {
            if (kk >= klen) break;
            ulonglong2 av = *(const ulonglong2*)&Ps[(kb + kk)*36 + rg*4];
            const ulonglong2* wp = (const ulonglong2*)&Wpd[kk*128 + cg*4];
            ulonglong2 wv0 = wp[0], wv1 = wp[1];
            FMA2(acc[0][0], av.x, wv0.x, acc[0][0]);
            FMA2(acc[1][0], av.y, wv0.x, acc[1][0]);
            FMA2(acc[0][1], av.x, wv0.y, acc[0][1]);
            FMA2(acc[1][1], av.y, wv0.y, acc[1][1]);
            FMA2(acc[0][2], av.x, wv1.x, acc[0][2]);
            FMA2(acc[1][2], av.y, wv1.x, acc[1][2]);
            FMA2(acc[0][3], av.x, wv1.y, acc[0][3]);
            FMA2(acc[1][3], av.y, wv1.y, acc[1][3]);
        }
    }
#pragma unroll
    for (int p = 0; p < 2; ++p) {
#pragma unroll
        for (int oo = 0; oo < 4; ++oo) {
            float lo, hi;
            unpack2(acc[p][oo], lo, hi);
            int o = cg*4 + oo;
            float bb = bs[o];
            int rowA = row0 + rg*4 + 2*p;
            int rowB = rowA + 1;
            {
                int sA = rowA >> 13, bA = (rowA >> 9) & 15, pA = rowA & 511;
                outF[(size_t)bA*(384*512) + (size_t)(sA*128 + o)*512 + pA] = fmaxf(lo + bb, 0.f);
            }
            {
                int sB = rowB >> 13, bB = (rowB >> 9) & 15, pB = rowB & 511;
                outF[(size_t)bB*(384*512) + (size_t)(sB*128 + o)*512 + pB] = fmaxf(hi + bb, 0.f);
            }
        }
    }
}

// ---------------------------------------------------------------------------
extern "C" void kernel_launch(void* const* d_in, const int* in_sizes, int n_in,
                              void* d_out, int out_size) {
    const float* xyz  = (const float*)d_in[0];
    const float* feat = (const float*)d_in[1];
    const float* W1   = (const float*)d_in[2];
    const float* b1   = (const float*)d_in[3];
    const float* W2   = (const float*)d_in[4];
    const float* b2   = (const float*)d_in[5];
    const float* Wcr  = (const float*)d_in[6];
    const float* bcr  = (const float*)d_in[7];
    float* out      = (float*)d_out;
    float* out_xyz  = out;                 // (B,512,3)
    float* outF     = out + Bn*NP*3;       // (B,384,512)

    k_transpose<<<dim3(4, 64, 16), dim3(32, 8)>>>(feat);
    k_fps<<<16, 1024>>>(xyz, out_xyz);
    k_msg<<<8192, 192>>>(xyz, W1, b1, W2, b2, out_xyz);
    k_proj<<<768, 256>>>(Wcr, bcr, outF);
}

// round 3
// speedup vs baseline: 1.0594x; 1.0594x over previous
#include <cuda_runtime.h>
#include <cstddef>

#define Bn 16
#define Nn 2048
#define Cn 128
#define NP 512
#define CIN 131
#define CPW2 160          // padded W2 row
#define PROW 132
#define NROWS (3*Bn*NP)

__device__ float g_featT[Bn*Nn*Cn];      // features transposed (B,N,C)
__device__ float g_pooled[NROWS*PROW];   // pooled rows (row = s*8192 + b*512 + p)

// ---------------------------------------------------------------------------
// K0 (fused): blocks [0,16) = FPS (one per batch); blocks [16,1040) = feature
// transpose (4 tiles of 32x32 per block). Transpose hides under FPS latency.
// ---------------------------------------------------------------------------
__global__ __launch_bounds__(1024) void k_pre(const float* __restrict__ xyz,
                                              const float* __restrict__ feat,
                                              float* __restrict__ out_xyz) {
    if (blockIdx.x < 16) {
        // ----- farthest point sampling, one BAR/iter -----
        __shared__ float xs[Nn], ys[Nn], zs[Nn];
        __shared__ float rv[2][32];
        __shared__ int   ri[2][32];
        int b = blockIdx.x, tid = threadIdx.x;
        int lane = tid & 31, wid = tid >> 5;
        const float* src = xyz + (size_t)b * Nn * 3;
        for (int t = tid; t < Nn; t += 1024) {
            xs[t] = src[t*3 + 0]; ys[t] = src[t*3 + 1]; zs[t] = src[t*3 + 2];
        }
        __syncthreads();
        int i0 = tid, i1 = tid + 1024;
        float x0 = xs[i0], y0 = ys[i0], z0 = zs[i0];
        float x1 = xs[i1], y1 = ys[i1], z1 = zs[i1];
        float d0 = 1e10f, d1 = 1e10f;
        int last = 0;
        if (tid == 0) {
            out_xyz[(size_t)b*NP*3 + 0] = xs[0];
            out_xyz[(size_t)b*NP*3 + 1] = ys[0];
            out_xyz[(size_t)b*NP*3 + 2] = zs[0];
        }
        for (int it = 1; it < NP; ++it) {
            float px = xs[last], py = ys[last], pz = zs[last];
            float ax = x0 - px, ay = y0 - py, az = z0 - pz;
            float dd = __fadd_rn(__fadd_rn(__fmul_rn(ax,ax), __fmul_rn(ay,ay)), __fmul_rn(az,az));
            d0 = fminf(d0, dd);
            ax = x1 - px; ay = y1 - py; az = z1 - pz;
            dd = __fadd_rn(__fadd_rn(__fmul_rn(ax,ax), __fmul_rn(ay,ay)), __fmul_rn(az,az));
            d1 = fminf(d1, dd);
            float v; int ix;
            if (d1 > d0) { v = d1; ix = i1; } else { v = d0; ix = i0; }
#pragma unroll
            for (int off = 16; off; off >>= 1) {
                float ov = __shfl_xor_sync(0xffffffffu, v, off);
                int   oi = __shfl_xor_sync(0xffffffffu, ix, off);
                if (ov > v || (ov == v && oi < ix)) { v = ov; ix = oi; }
            }
            int bufi = it & 1;
            if (lane == 0) { rv[bufi][wid] = v; ri[bufi][wid] = ix; }
            __syncthreads();
            v = rv[bufi][lane]; ix = ri[bufi][lane];
#pragma unroll
            for (int off = 16; off; off >>= 1) {
                float ov = __shfl_xor_sync(0xffffffffu, v, off);
                int   oi = __shfl_xor_sync(0xffffffffu, ix, off);
                if (ov > v || (ov == v && oi < ix)) { v = ov; ix = oi; }
            }
            last = ix;
            if (tid == 0) {
                out_xyz[(size_t)(b*NP + it)*3 + 0] = xs[ix];
                out_xyz[(size_t)(b*NP + it)*3 + 1] = ys[ix];
                out_xyz[(size_t)(b*NP + it)*3 + 2] = zs[ix];
            }
        }
    } else {
        // ----- transpose features (B,C,N) -> (B,N,C), 4 tiles per block -----
        __shared__ float tile[4][32][33];
        int sub = threadIdx.x >> 8;            // 0..3
        int t   = threadIdx.x & 255;
        int tx  = t & 31, ty = t >> 5;         // ty 0..7
        int tl  = (blockIdx.x - 16) * 4 + sub; // tile id 0..4095
        int b   = tl >> 8;
        int rem = tl & 255;
        int c0  = (rem & 3) * 32, n0 = (rem >> 2) * 32;
        const float* src = feat + (size_t)b * Cn * Nn;
        float* dst = g_featT + (size_t)b * Nn * Cn;
#pragma unroll
        for (int j = 0; j < 32; j += 8)
            tile[sub][ty + j][tx] = src[(size_t)(c0 + ty + j) * Nn + n0 + tx];
        __syncthreads();
#pragma unroll
        for (int j = 0; j < 32; j += 8)
            dst[(size_t)(n0 + ty + j) * Cn + c0 + tx] = tile[sub][tx][ty + j];
    }
}

// ---------------------------------------------------------------------------
// K2: ball query (warps 0-2) + MLP (plain FFMA, 8 samples/group, balanced
// static scale->warp map: w0->s0, w1-2->s1, w3-5->s2; 16 samples per warp)
// + register max-pool, NO atomics. 192 threads, one block per (b,center).
// ---------------------------------------------------------------------------
__global__ __launch_bounds__(192) void k_msg(const float* __restrict__ xyz,
                                             const float* __restrict__ W1,
                                             const float* __restrict__ b1,
                                             const float* __restrict__ W2,
                                             const float* __restrict__ b2,
                                             const float* __restrict__ new_xyz) {
    __shared__ float W2s[32*CPW2];
    __shared__ float b2s[CPW2];
    __shared__ float W1s[320];
    __shared__ float b1s[32];
    __shared__ __align__(16) float h1buf[6*32*8];   // [warp][m][q]
    __shared__ float rel_sh[6][8][3];
    __shared__ float pw[6*CPW2];
    __shared__ int   idx_sh[96];

    int tid = threadIdx.x, lane = tid & 31, w = tid >> 5;
    int blk = blockIdx.x, b = blk >> 9;
    const float* bp = xyz + (size_t)b * Nn * 3;

    for (int i = tid; i < 32*CPW2; i += 192) {
        int m = i / CPW2, c = i - m * CPW2;
        W2s[i] = (c < CIN) ? W2[m*CIN + c] : 0.f;
    }
    for (int i = tid; i < CPW2; i += 192) b2s[i] = (i < CIN) ? b2[i] : 0.f;
    for (int i = tid; i < 320; i += 192) W1s[i] = W1[i];
    if (tid < 32) b1s[tid] = b1[tid];

    float cx = new_xyz[(size_t)blk*3 + 0];
    float cy = new_xyz[(size_t)blk*3 + 1];
    float cz = new_xyz[(size_t)blk*3 + 2];

    // ---- ball query: first ns ascending indices with d2 < r^2, pad w/ first
    if (w < 3) {
        const float thr = (w == 0) ? (float)(0.1*0.1) : (w == 1) ? (float)(0.2*0.2) : (float)(0.4*0.4);
        const int   ns  = (w == 0) ? 16 : (w == 1) ? 32 : 48;
        const int   off = (w == 0) ? 0  : (w == 1) ? 16 : 48;
        int cnt = 0;
#pragma unroll 1
        for (int ch = 0; ch < 16; ++ch) {
            if (cnt >= ns) break;
            float d2v[4];
#pragma unroll
            for (int u = 0; u < 4; ++u) {
                int i = (ch*4 + u)*32 + lane;
                float qx = bp[i*3 + 0], qy = bp[i*3 + 1], qz = bp[i*3 + 2];
                float ax = cx - qx, ay = cy - qy, az = cz - qz;
                d2v[u] = __fadd_rn(__fadd_rn(__fmul_rn(ax,ax), __fmul_rn(ay,ay)), __fmul_rn(az,az));
            }
#pragma unroll
            for (int u = 0; u < 4; ++u) {
                bool pr = d2v[u] < thr;
                unsigned mk = __ballot_sync(0xffffffffu, pr);
                if (pr) {
                    int pos = cnt + __popc(mk & ((1u << lane) - 1u));
                    if (pos < ns) idx_sh[off + pos] = (ch*4 + u)*32 + lane;
                }
                cnt += __popc(mk);
            }
        }
        __syncwarp();
        if (cnt < ns) {
            int f0 = idx_sh[off];
            for (int q = cnt + lane; q < ns; q += 32) idx_sh[off + q] = f0;
        }
    }
    __syncthreads();

    // ---- static map: each warp owns 16 samples of one scale
    int s    = (w == 0) ? 0 : (w < 3) ? 1 : 2;
    int sb   = (s == 0) ? 0 : (s == 1) ? 16 : 48;
    int base = (s == 1) ? (w - 1)*16 : (s == 2) ? (w - 3)*16 : 0;

    const float* ftb = g_featT + (size_t)b * Nn * Cn;
    float lmax[5] = {0.f, 0.f, 0.f, 0.f, 0.f};

#pragma unroll 1
    for (int g2 = 0; g2 < 2; ++g2) {
        int j0 = base + g2*8;
        int sidx[8];
        float h1v[8];
#pragma unroll
        for (int q = 0; q < 8; ++q) {
            int ii = idx_sh[sb + j0 + q];
            sidx[q] = ii;
            float gx = bp[ii*3 + 0], gy = bp[ii*3 + 1], gz = bp[ii*3 + 2];
            float rx = gx - cx, ry = gy - cy, rz = gz - cz;
            if (lane == q) { rel_sh[w][q][0] = rx; rel_sh[w][q][1] = ry; rel_sh[w][q][2] = rz; }
            float dn = sqrtf(rx*rx + ry*ry + rz*rz);
            float a = b1s[lane];
            a = fmaf(dn, W1s[0*32 + lane], a);
            a = fmaf(cx, W1s[1*32 + lane], a);
            a = fmaf(cy, W1s[2*32 + lane], a);
            a = fmaf(cz, W1s[3*32 + lane], a);
            a = fmaf(gx, W1s[4*32 + lane], a);
            a = fmaf(gy, W1s[5*32 + lane], a);
            a = fmaf(gz, W1s[6*32 + lane], a);
            a = fmaf(rx, W1s[7*32 + lane], a);
            a = fmaf(ry, W1s[8*32 + lane], a);
            a = fmaf(rz, W1s[9*32 + lane], a);
            h1v[q] = fmaxf(a, 0.f);
        }
        __syncwarp();
        {
            float* hb = &h1buf[(w*32 + lane)*8];
            *(float4*)hb       = make_float4(h1v[0], h1v[1], h1v[2], h1v[3]);
            *(float4*)(hb + 4) = make_float4(h1v[4], h1v[5], h1v[6], h1v[7]);
        }
        __syncwarp();

        float acc[5][8];
#pragma unroll
        for (int i = 0; i < 5; ++i) {
            float bb = b2s[i*32 + lane];
#pragma unroll
            for (int q = 0; q < 8; ++q) acc[i][q] = bb;
        }
#pragma unroll 4
        for (int m = 0; m < 32; ++m) {
            const float4* hp = (const float4*)&h1buf[(w*32 + m)*8];
            float4 Ha = hp[0];
            float4 Hb = hp[1];
#pragma unroll
            for (int i = 0; i < 5; ++i) {
                float ww = W2s[m*CPW2 + i*32 + lane];
                acc[i][0] = fmaf(ww, Ha.x, acc[i][0]);
                acc[i][1] = fmaf(ww, Ha.y, acc[i][1]);
                acc[i][2] = fmaf(ww, Ha.z, acc[i][2]);
                acc[i][3] = fmaf(ww, Ha.w, acc[i][3]);
                acc[i][4] = fmaf(ww, Hb.x, acc[i][4]);
                acc[i][5] = fmaf(ww, Hb.y, acc[i][5]);
                acc[i][6] = fmaf(ww, Hb.z, acc[i][6]);
                acc[i][7] = fmaf(ww, Hb.w, acc[i][7]);
            }
        }

        // epilogue: relu(h*x) running max (lmax stays >= 0)
#pragma unroll
        for (int i = 0; i < 5; ++i) {
            int c = i*32 + lane;
            if (c < CIN) {
#pragma unroll
                for (int q = 0; q < 8; ++q) {
                    float xv;
                    if (i == 0) {
                        xv = (c >= 3) ? ftb[(size_t)sidx[q]*Cn + c - 3]
                                      : rel_sh[w][q][c];
                    } else {
                        xv = ftb[(size_t)sidx[q]*Cn + c - 3];
                    }
                    lmax[i] = fmaxf(lmax[i], acc[i][q] * xv);
                }
            }
        }
    }
#pragma unroll
    for (int i = 0; i < 5; ++i) pw[w*CPW2 + i*32 + lane] = lmax[i];
    __syncthreads();

    // merge warps of same scale, write g_pooled
    for (int o = tid; o < 3*CIN; o += 192) {
        int sc = o / CIN, c = o - sc*CIN;
        float v;
        if (sc == 0)      v = pw[0*CPW2 + c];
        else if (sc == 1) v = fmaxf(pw[1*CPW2 + c], pw[2*CPW2 + c]);
        else              v = fmaxf(fmaxf(pw[3*CPW2 + c], pw[4*CPW2 + c]), pw[5*CPW2 + c]);
        g_pooled[(size_t)(sc*8192 + blk)*PROW + c] = v;
    }
}

// ---------------------------------------------------------------------------
// K3: out = relu(pooled @ Wcr + bcr), M=24576 K=131 N=128, 3 k-panels.
// ---------------------------------------------------------------------------
__global__ __launch_bounds__(256) void k_proj(const float* __restrict__ Wcr,
                                              const float* __restrict__ bcr,
                                              float* __restrict__ outF) {
    __shared__ __align__(16) float Ps[131*36];   // [k][r], stride 36
    __shared__ __align__(16) float Wp[48*128];
    __shared__ float bs[128];
    int tid = threadIdx.x;
    int row0 = blockIdx.x * 32;
    for (int idx = tid; idx < 32*131; idx += 256) {
        int r = idx / 131, k = idx - r*131;
        Ps[k*36 + r] = g_pooled[(size_t)(row0 + r)*PROW + k];
    }
    if (tid < 128) bs[tid] = bcr[tid];
    float acc[4][4];
#pragma unroll
    for (int r = 0; r < 4; ++r)
#pragma unroll
        for (int o = 0; o < 4; ++o) acc[r][o] = 0.f;
    int cg = tid & 31, rg = tid >> 5;
    const int kb_tab[4] = {0, 48, 96, 131};
    for (int p = 0; p < 3; ++p) {
        int kb = kb_tab[p];
        int klen = kb_tab[p + 1] - kb;
        __syncthreads();
        for (int j = tid; j < klen*128; j += 256) Wp[j] = Wcr[kb*128 + j];
        __syncthreads();
#pragma unroll 4
        for (int kk = 0; kk < klen; ++kk) {
            float4 wv = *(const float4*)&Wp[kk*128 + cg*4];
            float4 av = *(const float4*)&Ps[(kb + kk)*36 + rg*4];
            acc[0][0] = fmaf(av.x, wv.x, acc[0][0]);
            acc[0][1] = fmaf(av.x, wv.y, acc[0][1]);
            acc[0][2] = fmaf(av.x, wv.z, acc[0][2]);
            acc[0][3] = fmaf(av.x, wv.w, acc[0][3]);
            acc[1][0] = fmaf(av.y, wv.x, acc[1][0]);
            acc[1][1] = fmaf(av.y, wv.y, acc[1][1]);
            acc[1][2] = fmaf(av.y, wv.z, acc[1][2]);
            acc[1][3] = fmaf(av.y, wv.w, acc[1][3]);
            acc[2][0] = fmaf(av.z, wv.x, acc[2][0]);
            acc[2][1] = fmaf(av.z, wv.y, acc[2][1]);
            acc[2][2] = fmaf(av.z, wv.z, acc[2][2]);
            acc[2][3] = fmaf(av.z, wv.w, acc[2][3]);
            acc[3][0] = fmaf(av.w, wv.x, acc[3][0]);
            acc[3][1] = fmaf(av.w, wv.y, acc[3][1]);
            acc[3][2] = fmaf(av.w, wv.z, acc[3][2]);
            acc[3][3] = fmaf(av.w, wv.w, acc[3][3]);
        }
    }
#pragma unroll
    for (int rr = 0; rr < 4; ++rr) {
        int row = row0 + rg*4 + rr;
        int s  = row >> 13;
        int bb = (row >> 9) & 15;
        int pp = row & 511;
        size_t obase = (size_t)bb*(384*512) + (size_t)(s*128)*512 + pp;
#pragma unroll
        for (int oo = 0; oo < 4; ++oo) {
            float v = acc[rr][oo] + bs[cg*4 + oo];
            outF[obase + (size_t)(cg*4 + oo)*512] = fmaxf(v, 0.f);
        }
    }
}

// ---------------------------------------------------------------------------
extern "C" void kernel_launch(void* const* d_in, const int* in_sizes, int n_in,
                              void* d_out, int out_size) {
    const float* xyz  = (const float*)d_in[0];
    const float* feat = (const float*)d_in[1];
    const float* W1   = (const float*)d_in[2];
    const float* b1   = (const float*)d_in[3];
    const float* W2   = (const float*)d_in[4];
    const float* b2   = (const float*)d_in[5];
    const float* Wcr  = (const float*)d_in[6];
    const float* bcr  = (const float*)d_in[7];
    float* out      = (float*)d_out;
    float* out_xyz  = out;                 // (B,512,3)
    float* outF     = out + Bn*NP*3;       // (B,384,512)

    k_pre<<<16 + 1024, 1024>>>(xyz, feat, out_xyz);
    k_msg<<<8192, 192>>>(xyz, W1, b1, W2, b2, out_xyz);
    k_proj<<<768, 256>>>(Wcr, bcr, outF);
}

// round 4
// speedup vs baseline: 1.4031x; 1.3243x over previous
#include <cuda_runtime.h>
#include <cstddef>

#define Bn 16
#define Nn 2048
#define Cn 128
#define NP 512
#define CIN 131
#define CPW2 160
#define PROW 132
#define NROWS (3*Bn*NP)

__device__ float g_featT[Bn*Nn*Cn];      // features transposed (B,N,C)
__device__ float g_pooled[NROWS*PROW];   // pooled rows (row = s*8192 + b*512 + p)

// ---------------------------------------------------------------------------
// K0 (fused, 256 threads): blocks [0,16) = FPS (one per batch, 8 pts/thread,
// redux-based argmax); blocks [16,16+4096) = feature transpose (1 tile each).
// ---------------------------------------------------------------------------
__global__ __launch_bounds__(256) void k_pre(const float* __restrict__ xyz,
                                             const float* __restrict__ feat,
                                             float* __restrict__ out_xyz) {
    if (blockIdx.x < 16) {
        __shared__ float xs[Nn], ys[Nn], zs[Nn];
        __shared__ unsigned rvb[2][8];
        __shared__ int      rib[2][8];
        int b = blockIdx.x, tid = threadIdx.x;
        int lane = tid & 31, w = tid >> 5;
        const float* src = xyz + (size_t)b * Nn * 3;
        for (int t = tid; t < Nn; t += 256) {
            xs[t] = src[t*3 + 0]; ys[t] = src[t*3 + 1]; zs[t] = src[t*3 + 2];
        }
        __syncthreads();
        float X[8], Y[8], Z[8], D[8];
#pragma unroll
        for (int q = 0; q < 8; ++q) {
            int i = tid*8 + q;
            X[q] = xs[i]; Y[q] = ys[i]; Z[q] = zs[i];
            D[q] = 1e10f;
        }
        int last = 0;
        if (tid == 0) {
            out_xyz[(size_t)b*NP*3 + 0] = xs[0];
            out_xyz[(size_t)b*NP*3 + 1] = ys[0];
            out_xyz[(size_t)b*NP*3 + 2] = zs[0];
        }
        for (int it = 1; it < NP; ++it) {
            float px = xs[last], py = ys[last], pz = zs[last];
#pragma unroll
            for (int q = 0; q < 8; ++q) {
                float ax = X[q] - px, ay = Y[q] - py, az = Z[q] - pz;
                float dd = __fadd_rn(__fadd_rn(__fmul_rn(ax,ax), __fmul_rn(ay,ay)),
                                     __fmul_rn(az,az));
                D[q] = fminf(D[q], dd);
            }
            // local argmax, ties -> lowest q (strict >)
            float va = D[0]; int ia = 0;
            if (D[1] > va) { va = D[1]; ia = 1; }
            float vb = D[2]; int ib = 2;
            if (D[3] > vb) { vb = D[3]; ib = 3; }
            float vc = D[4]; int ic = 4;
            if (D[5] > vc) { vc = D[5]; ic = 5; }
            float vd = D[6]; int id_ = 6;
            if (D[7] > vd) { vd = D[7]; id_ = 7; }
            if (vb > va) { va = vb; ia = ib; }
            if (vd > vc) { vc = vd; ic = id_; }
            if (vc > va) { va = vc; ia = ic; }
            // warp argmax via redux on bits (nonneg float -> monotone)
            unsigned bits = __float_as_uint(va);
            unsigned m = __reduce_max_sync(0xffffffffu, bits);
            unsigned bal = __ballot_sync(0xffffffffu, bits == m);
            int srcl = __ffs(bal) - 1;
            int lloc = __shfl_sync(0xffffffffu, ia, srcl);
            int bufi = it & 1;
            if (lane == 0) {
                rvb[bufi][w] = m;
                rib[bufi][w] = (w*32 + srcl)*8 + lloc;
            }
            __syncthreads();
            // cross-warp (8 partials), redundant in every warp
            int j = lane & 7;
            unsigned v2 = rvb[bufi][j];
            int      i2 = rib[bufi][j];
            unsigned m2 = __reduce_max_sync(0xffffffffu, v2);
            unsigned b2 = __ballot_sync(0xffffffffu, v2 == m2);
            int s2 = __ffs(b2) - 1;   // lowest lane -> lowest warp -> lowest idx
            last = __shfl_sync(0xffffffffu, i2, s2);
            if (tid == 0) {
                out_xyz[(size_t)(b*NP + it)*3 + 0] = xs[last];
                out_xyz[(size_t)(b*NP + it)*3 + 1] = ys[last];
                out_xyz[(size_t)(b*NP + it)*3 + 2] = zs[last];
            }
        }
    } else {
        // transpose features (B,C,N) -> (B,N,C), one 32x32 tile per block
        __shared__ float tile[32][33];
        int tl  = blockIdx.x - 16;       // 0..4095
        int b   = tl >> 8;
        int rem = tl & 255;
        int c0  = (rem & 3) * 32, n0 = (rem >> 2) * 32;
        int tx = threadIdx.x & 31, ty = threadIdx.x >> 5;   // ty 0..7
        const float* src = feat + (size_t)b * Cn * Nn;
        float* dst = g_featT + (size_t)b * Nn * Cn;
#pragma unroll
        for (int j = 0; j < 32; j += 8)
            tile[ty + j][tx] = src[(size_t)(c0 + ty + j) * Nn + n0 + tx];
        __syncthreads();
#pragma unroll
        for (int j = 0; j < 32; j += 8)
            dst[(size_t)(n0 + ty + j) * Cn + c0 + tx] = tile[tx][ty + j];
    }
}

// ---------------------------------------------------------------------------
// K2 (R1 version, measured best): ball query (warps 0-2) + MLP, 4 samples per
// warp-group, smem atomicMax pooling. 160 threads, one block per (b,center).
// ---------------------------------------------------------------------------
__global__ __launch_bounds__(160) void k_msg(const float* __restrict__ xyz,
                                             const float* __restrict__ W1,
                                             const float* __restrict__ b1,
                                             const float* __restrict__ W2,
                                             const float* __restrict__ b2,
                                             const float* __restrict__ new_xyz) {
    __shared__ float W1s[10*32];
    __shared__ float b1s[32];
    __shared__ float W2s[32*CPW2];
    __shared__ float b2s[CPW2];
    __shared__ int   idx_sh[96];
    __shared__ float h1buf[5*32*4];
    __shared__ int   pooled_sh[3*132];
    int tid = threadIdx.x, lane = tid & 31, w = tid >> 5;
    int blk = blockIdx.x, b = blk >> 9;
    const float* bp  = xyz + (size_t)b * Nn * 3;

    for (int i = tid; i < 320; i += 160) W1s[i] = W1[i];
    if (tid < 32) b1s[tid] = b1[tid];
    for (int i = tid; i < 32*CPW2; i += 160) {
        int m = i / CPW2, c = i - m * CPW2;
        W2s[i] = (c < CIN) ? W2[m*CIN + c] : 0.f;
    }
    for (int i = tid; i < CPW2; i += 160) b2s[i] = (i < CIN) ? b2[i] : 0.f;
    for (int i = tid; i < 3*132; i += 160) pooled_sh[i] = 0;

    float cx = new_xyz[(size_t)blk*3 + 0];
    float cy = new_xyz[(size_t)blk*3 + 1];
    float cz = new_xyz[(size_t)blk*3 + 2];

    if (w < 3) {
        const float thr = (w == 0) ? (float)(0.1*0.1) : (w == 1) ? (float)(0.2*0.2) : (float)(0.4*0.4);
        const int   ns  = (w == 0) ? 16 : (w == 1) ? 32 : 48;
        const int   off = (w == 0) ? 0  : (w == 1) ? 16 : 48;
        int cnt = 0;
        for (int ch = 0; ch < 64 && cnt < ns; ++ch) {
            int i = ch*32 + lane;
            float qx = bp[i*3 + 0], qy = bp[i*3 + 1], qz = bp[i*3 + 2];
            float ax = cx - qx, ay = cy - qy, az = cz - qz;
            float d2 = __fadd_rn(__fadd_rn(__fmul_rn(ax,ax), __fmul_rn(ay,ay)), __fmul_rn(az,az));
            bool pr = d2 < thr;
            unsigned mk = __ballot_sync(0xffffffffu, pr);
            if (pr) {
                int pos = cnt + __popc(mk & ((1u << lane) - 1u));
                if (pos < ns) idx_sh[off + pos] = i;
            }
            cnt += __popc(mk);
        }
        __syncwarp();
        if (cnt < ns) {
            int f0 = idx_sh[off];
            for (int q = cnt + lane; q < ns; q += 32) idx_sh[off + q] = f0;
        }
    }
    __syncthreads();

    const float* ftb = g_featT + (size_t)b * Nn * Cn;
    for (int g = w; g < 24; g += 5) {
        int s, sb, j0;
        if (g < 4)       { s = 0; sb = 0;  j0 = g * 4; }
        else if (g < 12) { s = 1; sb = 16; j0 = (g - 4) * 4; }
        else             { s = 2; sb = 48; j0 = (g - 12) * 4; }
        int sidx[4]; float relx[4], rely[4], relz[4], h1v[4];
#pragma unroll
        for (int q = 0; q < 4; ++q) {
            int ii = idx_sh[sb + j0 + q];
            sidx[q] = ii;
            float gx = bp[ii*3 + 0], gy = bp[ii*3 + 1], gz = bp[ii*3 + 2];
            float rx = gx - cx, ry = gy - cy, rz = gz - cz;
            relx[q] = rx; rely[q] = ry; relz[q] = rz;
            float dn = sqrtf(rx*rx + ry*ry + rz*rz);
            float a = b1s[lane];
            a = fmaf(dn, W1s[0*32 + lane], a);
            a = fmaf(cx, W1s[1*32 + lane], a);
            a = fmaf(cy, W1s[2*32 + lane], a);
            a = fmaf(cz, W1s[3*32 + lane], a);
            a = fmaf(gx, W1s[4*32 + lane], a);
            a = fmaf(gy, W1s[5*32 + lane], a);
            a = fmaf(gz, W1s[6*32 + lane], a);
            a = fmaf(rx, W1s[7*32 + lane], a);
            a = fmaf(ry, W1s[8*32 + lane], a);
            a = fmaf(rz, W1s[9*32 + lane], a);
            h1v[q] = fmaxf(a, 0.f);
        }
        __syncwarp();
        *(float4*)&h1buf[(w*32 + lane)*4] = make_float4(h1v[0], h1v[1], h1v[2], h1v[3]);
        __syncwarp();

        float acc[5][4];
#pragma unroll
        for (int i = 0; i < 5; ++i) {
            float bb = b2s[i*32 + lane];
            acc[i][0] = bb; acc[i][1] = bb; acc[i][2] = bb; acc[i][3] = bb;
        }
#pragma unroll 4
        for (int m = 0; m < 32; ++m) {
            float4 H = *(const float4*)&h1buf[(w*32 + m)*4];
#pragma unroll
            for (int i = 0; i < 5; ++i) {
                float ww = W2s[m*CPW2 + i*32 + lane];
                acc[i][0] = fmaf(ww, H.x, acc[i][0]);
                acc[i][1] = fmaf(ww, H.y, acc[i][1]);
                acc[i][2] = fmaf(ww, H.z, acc[i][2]);
                acc[i][3] = fmaf(ww, H.w, acc[i][3]);
            }
        }
#pragma unroll
        for (int i = 0; i < 5; ++i) {
            int c = i*32 + lane;
            if (c < CIN) {
                float vmax = 0.f;
#pragma unroll
                for (int q = 0; q < 4; ++q) {
                    float xv;
                    if (c >= 3) xv = ftb[(size_t)sidx[q]*Cn + (c - 3)];
                    else        xv = (c == 0) ? relx[q] : (c == 1) ? rely[q] : relz[q];
                    float v = acc[i][q] * xv;
                    vmax = fmaxf(vmax, fmaxf(v, 0.f));
                }
                atomicMax(&pooled_sh[s*132 + c], __float_as_int(vmax)); // vmax >= 0
            }
        }
    }
    __syncthreads();
    for (int i = tid; i < 3*CIN; i += 160) {
        int s = i / CIN, c = i - s*CIN;
        g_pooled[(size_t)(s*8192 + blk)*PROW + c] = __int_as_float(pooled_sh[s*132 + c]);
    }
}

// ---------------------------------------------------------------------------
// K3 (R1 version, measured 51.5us): relu(pooled @ Wcr + bcr), tiled GEMM.
// ---------------------------------------------------------------------------
__global__ __launch_bounds__(256) void k_proj(const float* __restrict__ Wcr,
                                              const float* __restrict__ bcr,
                                              float* __restrict__ outF) {
    __shared__ float Ps[131*36];
    __shared__ float Wp[32*128];
    __shared__ float bs[128];
    int tid = threadIdx.x;
    int row0 = blockIdx.x * 32;
    for (int idx = tid; idx < 32*131; idx += 256) {
        int r = idx / 131, k = idx - r*131;
        Ps[k*36 + r] = g_pooled[(size_t)(row0 + r)*PROW + k];
    }
    if (tid < 128) bs[tid] = bcr[tid];
    float acc[4][4];
#pragma unroll
    for (int r = 0; r < 4; ++r)
#pragma unroll
        for (int o = 0; o < 4; ++o) acc[r][o] = 0.f;
    int cg = tid & 31, rg = tid >> 5;
    for (int kp = 0; kp < 5; ++kp) {
        int kb = kp*32;
        int klen = (kp == 4) ? 3 : 32;
        __syncthreads();
        for (int idx = tid; idx < klen*128; idx += 256) Wp[idx] = Wcr[kb*128 + idx];
        __syncthreads();
        for (int kk = 0; kk < klen; ++kk) {
            float4 wv = *(const float4*)&Wp[kk*128 + cg*4];
            float4 av = *(const float4*)&Ps[(kb + kk)*36 + rg*4];
            acc[0][0] = fmaf(av.x, wv.x, acc[0][0]);
            acc[0][1] = fmaf(av.x, wv.y, acc[0][1]);
            acc[0][2] = fmaf(av.x, wv.z, acc[0][2]);
            acc[0][3] = fmaf(av.x, wv.w, acc[0][3]);
            acc[1][0] = fmaf(av.y, wv.x, acc[1][0]);
            acc[1][1] = fmaf(av.y, wv.y, acc[1][1]);
            acc[1][2] = fmaf(av.y, wv.z, acc[1][2]);
            acc[1][3] = fmaf(av.y, wv.w, acc[1][3]);
            acc[2][0] = fmaf(av.z, wv.x, acc[2][0]);
            acc[2][1] = fmaf(av.z, wv.y, acc[2][1]);
            acc[2][2] = fmaf(av.z, wv.z, acc[2][2]);
            acc[2][3] = fmaf(av.z, wv.w, acc[2][3]);
            acc[3][0] = fmaf(av.w, wv.x, acc[3][0]);
            acc[3][1] = fmaf(av.w, wv.y, acc[3][1]);
            acc[3][2] = fmaf(av.w, wv.z, acc[3][2]);
            acc[3][3] = fmaf(av.w, wv.w, acc[3][3]);
        }
    }
#pragma unroll
    for (int rr = 0; rr < 4; ++rr) {
        int row = row0 + rg*4 + rr;
        int s  = row >> 13;
        int bb = (row >> 9) & 15;
        int pp = row & 511;
        size_t obase = (size_t)bb*(384*512) + (size_t)(s*128)*512 + pp;
#pragma unroll
        for (int oo = 0; oo < 4; ++oo) {
            float v = acc[rr][oo] + bs[cg*4 + oo];
            outF[obase + (size_t)(cg*4 + oo)*512] = fmaxf(v, 0.f);
        }
    }
}

// ---------------------------------------------------------------------------
extern "C" void kernel_launch(void* const* d_in, const int* in_sizes, int n_in,
                              void* d_out, int out_size) {
    const float* xyz  = (const float*)d_in[0];
    const float* feat = (const float*)d_in[1];
    const float* W1   = (const float*)d_in[2];
    const float* b1   = (const float*)d_in[3];
    const float* W2   = (const float*)d_in[4];
    const float* b2   = (const float*)d_in[5];
    const float* Wcr  = (const float*)d_in[6];
    const float* bcr  = (const float*)d_in[7];
    float* out      = (float*)d_out;
    float* out_xyz  = out;                 // (B,512,3)
    float* outF     = out + Bn*NP*3;       // (B,384,512)

    k_pre<<<16 + 4096, 256>>>(xyz, feat, out_xyz);
    k_msg<<<8192, 160>>>(xyz, W1, b1, W2, b2, out_xyz);
    k_proj<<<768, 256>>>(Wcr, bcr, outF);
}